// round 2
// baseline (speedup 1.0000x reference)
#include <cuda_runtime.h>
#include <cstdint>

// MusicRNN: 2-layer LSTM (B=2048, T=256, I=88, H=64) + FC(64->13)
//   K1: precompute layer-0 input projection P0 (gate-interleaved float4).
//   K2: persistent fused recurrence. 128 CTAs x 256 threads (8 warps = 2/SMSP),
//       16 batch rows/CTA, 4 rows/thread, weights in SMEM (gate-packed float4),
//       h via SMEM double buffer, c in registers, packed fma.rn.f32x2.

#define BB 2048
#define TT 256
#define II 88
#define HH 64
#define OO 13

// Scratch for the precomputed input projection: [T][B][H] float4 = 512 MB.
__device__ float4 g_P0[(size_t)TT * BB * HH];

// ---------------- packed f32x2 helpers ----------------
__device__ __forceinline__ unsigned long long pack2(float lo, float hi) {
    unsigned long long r;
    asm("mov.b64 %0, {%1, %2};" : "=l"(r) : "f"(lo), "f"(hi));
    return r;
}
__device__ __forceinline__ unsigned long long dup2(float v) {
    unsigned long long r;
    asm("mov.b64 %0, {%1, %1};" : "=l"(r) : "f"(v));
    return r;
}
__device__ __forceinline__ void unpack2(unsigned long long v, float& lo, float& hi) {
    asm("mov.b64 {%0, %1}, %2;" : "=f"(lo), "=f"(hi) : "l"(v));
}
__device__ __forceinline__ void fma2(unsigned long long& d, unsigned long long a,
                                     unsigned long long b) {
    asm("fma.rn.f32x2 %0, %1, %2, %0;" : "+l"(d) : "l"(a), "l"(b));
}

// ---------------- activations (MUFU-based, ~1e-7 rel err) ----------------
__device__ __forceinline__ float sigf(float x) {
    return __fdividef(1.0f, 1.0f + __expf(-x));
}
__device__ __forceinline__ float tanhf_fast(float x) {
    return __fdividef(2.0f, 1.0f + __expf(-2.0f * x)) - 1.0f;
}

__device__ __forceinline__ void lstm_act_pair(
    unsigned long long aI, unsigned long long aF,
    unsigned long long aG, unsigned long long aO,
    float* c, float* hn, int r)
{
    float i0, i1, f0, f1, g0, g1, o0, o1;
    unpack2(aI, i0, i1); unpack2(aF, f0, f1);
    unpack2(aG, g0, g1); unpack2(aO, o0, o1);
    float cc0 = sigf(f0) * c[r]     + sigf(i0) * tanhf_fast(g0);
    float cc1 = sigf(f1) * c[r + 1] + sigf(i1) * tanhf_fast(g1);
    c[r]      = cc0;  hn[r]     = sigf(o0) * tanhf_fast(cc0);
    c[r + 1]  = cc1;  hn[r + 1] = sigf(o1) * tanhf_fast(cc1);
}

// =====================================================================
// K1: input projection.  Grid: B*T/64 CTAs, 512 threads (64 h x 8 rowgroups),
//     8 (b,t)-rows per thread, K=88.  (unchanged — 4 warps/SMSP already)
// =====================================================================
#define K1_SMEM ((5696 * 16) + (II * 64 * 4))   // w0p+b0p (float4) + xs (float)

__global__ void __launch_bounds__(512) k1_inproj(
    const float* __restrict__ x, const float* __restrict__ w_ih0,
    const float* __restrict__ b_ih0, const float* __restrict__ b_hh0)
{
    extern __shared__ float4 sm4[];
    float4* w0p = sm4;                      // [88][64] gate-packed
    float4* b0p = sm4 + II * HH;            // [64]
    float*  xs  = (float*)(sm4 + II * HH + HH);  // [88][64]  (k-major, row minor)

    const int tid = threadIdx.x;

    for (int idx = tid; idx < II * HH; idx += 512) {
        int k = idx >> 6, h = idx & 63;
        float4 v;
        v.x = w_ih0[(h      ) * II + k];
        v.y = w_ih0[(h +  64) * II + k];
        v.z = w_ih0[(h + 128) * II + k];
        v.w = w_ih0[(h + 192) * II + k];
        w0p[idx] = v;
    }
    if (tid < HH) {
        float4 v;
        v.x = b_ih0[tid]       + b_hh0[tid];
        v.y = b_ih0[tid +  64] + b_hh0[tid +  64];
        v.z = b_ih0[tid + 128] + b_hh0[tid + 128];
        v.w = b_ih0[tid + 192] + b_hh0[tid + 192];
        b0p[tid] = v;
    }
    const int bt0 = blockIdx.x * 64;   // 64 consecutive (b*T+t) pairs, same b
    for (int idx = tid; idx < 64 * II; idx += 512) {
        int r = idx / II, k = idx - r * II;
        xs[(k << 6) + r] = x[(size_t)bt0 * II + idx];   // fully coalesced read
    }
    __syncthreads();

    const int h  = tid & 63;
    const int r0 = (tid >> 6) * 8;   // 8 rows per thread

    unsigned long long aI[4], aF[4], aG[4], aO[4];
    {
        float4 bv = b0p[h];
        #pragma unroll
        for (int p = 0; p < 4; p++) {
            aI[p] = dup2(bv.x); aF[p] = dup2(bv.y);
            aG[p] = dup2(bv.z); aO[p] = dup2(bv.w);
        }
    }
    #pragma unroll 4
    for (int k = 0; k < II; k++) {
        float4 w = w0p[(k << 6) + h];
        unsigned long long wi = dup2(w.x), wf = dup2(w.y),
                           wg = dup2(w.z), wo = dup2(w.w);
        const unsigned long long* hv =
            (const unsigned long long*)&xs[(k << 6) + r0];  // broadcast loads
        unsigned long long v0 = hv[0], v1 = hv[1], v2 = hv[2], v3 = hv[3];
        fma2(aI[0], wi, v0); fma2(aI[1], wi, v1); fma2(aI[2], wi, v2); fma2(aI[3], wi, v3);
        fma2(aF[0], wf, v0); fma2(aF[1], wf, v1); fma2(aF[2], wf, v2); fma2(aF[3], wf, v3);
        fma2(aG[0], wg, v0); fma2(aG[1], wg, v1); fma2(aG[2], wg, v2); fma2(aG[3], wg, v3);
        fma2(aO[0], wo, v0); fma2(aO[1], wo, v1); fma2(aO[2], wo, v2); fma2(aO[3], wo, v3);
    }
    #pragma unroll
    for (int p = 0; p < 4; p++) {
        float i0, i1, f0, f1, g0, g1, o0, o1;
        unpack2(aI[p], i0, i1); unpack2(aF[p], f0, f1);
        unpack2(aG[p], g0, g1); unpack2(aO[p], o0, o1);
        int bt = bt0 + r0 + 2 * p;
        int t = bt & (TT - 1), b = bt >> 8;
        g_P0[((size_t)t * BB + b) * HH + h] = make_float4(i0, f0, g0, o0);
        bt++; t = bt & (TT - 1); b = bt >> 8;
        g_P0[((size_t)t * BB + b) * HH + h] = make_float4(i1, f1, g1, o1);
    }
}

// =====================================================================
// K2: persistent fused recurrence + FC.
//     Grid: 128 CTAs x 256 threads (64 h x 4 rowgroups of 4 rows) = 16 rows/CTA.
// =====================================================================
#define K2_SMEM (((3 * 4096 + 64) * 16) + (2048 + 1024) * 4)   // 209920 B

__global__ void __launch_bounds__(256) k2_rnn(
    const float* __restrict__ w_hh0, const float* __restrict__ w_ih1,
    const float* __restrict__ w_hh1, const float* __restrict__ b_ih1,
    const float* __restrict__ b_hh1, const float* __restrict__ fc_w,
    const float* __restrict__ fc_b, float* __restrict__ out)
{
    extern __shared__ float4 sm4[];
    float4* w0p = sm4;                 // [64][64] gate-packed W_hh0
    float4* w1i = sm4 + 4096;          // W_ih1
    float4* w1h = sm4 + 8192;          // W_hh1
    float4* b1p = sm4 + 12288;         // [64] layer-1 bias
    float*  h0buf = (float*)(sm4 + 12352);   // 2 x [64][16] double buffer
    float*  h1s   = h0buf + 2048;            // [64][16]

    const int tid = threadIdx.x;

    for (int idx = tid; idx < 4096; idx += 256) {
        int k = idx >> 6, h = idx & 63;
        float4 v;
        v.x = w_hh0[(h      ) * HH + k]; v.y = w_hh0[(h +  64) * HH + k];
        v.z = w_hh0[(h + 128) * HH + k]; v.w = w_hh0[(h + 192) * HH + k];
        w0p[idx] = v;
        v.x = w_ih1[(h      ) * HH + k]; v.y = w_ih1[(h +  64) * HH + k];
        v.z = w_ih1[(h + 128) * HH + k]; v.w = w_ih1[(h + 192) * HH + k];
        w1i[idx] = v;
        v.x = w_hh1[(h      ) * HH + k]; v.y = w_hh1[(h +  64) * HH + k];
        v.z = w_hh1[(h + 128) * HH + k]; v.w = w_hh1[(h + 192) * HH + k];
        w1h[idx] = v;
    }
    if (tid < HH) {
        float4 v;
        v.x = b_ih1[tid]       + b_hh1[tid];
        v.y = b_ih1[tid +  64] + b_hh1[tid +  64];
        v.z = b_ih1[tid + 128] + b_hh1[tid + 128];
        v.w = b_ih1[tid + 192] + b_hh1[tid + 192];
        b1p[tid] = v;
    }
    for (int idx = tid; idx < 3072; idx += 256) h0buf[idx] = 0.0f;  // h0(both)+h1
    __syncthreads();

    const int h   = tid & 63;
    const int r0  = (tid >> 6) * 4;        // 0,4,8,12 -> 4 rows per thread
    const int bR0 = blockIdx.x * 16;       // batch base for this CTA

    float c0[4], c1[4];
    #pragma unroll
    for (int r = 0; r < 4; r++) { c0[r] = 0.0f; c1[r] = 0.0f; }

    // software-pipelined input-projection loads
    float4 xg[4];
    #pragma unroll
    for (int j = 0; j < 4; j++)
        xg[j] = g_P0[(size_t)(bR0 + r0 + j) * HH + h];   // t = 0

    for (int t = 0; t < TT; t++) {
        unsigned long long aI[2], aF[2], aG[2], aO[2];
        #pragma unroll
        for (int p = 0; p < 2; p++) {
            aI[p] = pack2(xg[2 * p].x, xg[2 * p + 1].x);
            aF[p] = pack2(xg[2 * p].y, xg[2 * p + 1].y);
            aG[p] = pack2(xg[2 * p].z, xg[2 * p + 1].z);
            aO[p] = pack2(xg[2 * p].w, xg[2 * p + 1].w);
        }
        {   // prefetch P0 for t+1 (overlaps with layer-0 matvec)
            int tn = (t + 1 < TT) ? (t + 1) : t;
            size_t base = ((size_t)tn * BB + bR0 + r0) * HH + h;
            #pragma unroll
            for (int j = 0; j < 4; j++) xg[j] = g_P0[base + (size_t)j * HH];
        }

        // ---- layer 0: gates += h0(t-1) @ W_hh0^T ----
        const float* hp = h0buf + (t & 1) * 1024;
        #pragma unroll 8
        for (int k = 0; k < HH; k++) {
            float4 w = w0p[(k << 6) + h];
            unsigned long long wi = dup2(w.x), wf = dup2(w.y),
                               wg = dup2(w.z), wo = dup2(w.w);
            ulonglong2 hv = *(const ulonglong2*)(hp + (k << 4) + r0);
            fma2(aI[0], wi, hv.x); fma2(aI[1], wi, hv.y);
            fma2(aF[0], wf, hv.x); fma2(aF[1], wf, hv.y);
            fma2(aG[0], wg, hv.x); fma2(aG[1], wg, hv.y);
            fma2(aO[0], wo, hv.x); fma2(aO[1], wo, hv.y);
        }
        float h0n[4];
        #pragma unroll
        for (int p = 0; p < 2; p++)
            lstm_act_pair(aI[p], aF[p], aG[p], aO[p], c0, h0n, 2 * p);

        float* hw = h0buf + ((t + 1) & 1) * 1024 + (h << 4) + r0;
        *(float4*)hw = make_float4(h0n[0], h0n[1], h0n[2], h0n[3]);
        __syncthreads();

        // ---- layer 1: gates = b1 + h0(t) @ W_ih1^T + h1(t-1) @ W_hh1^T ----
        {
            float4 bv = b1p[h];
            #pragma unroll
            for (int p = 0; p < 2; p++) {
                aI[p] = dup2(bv.x); aF[p] = dup2(bv.y);
                aG[p] = dup2(bv.z); aO[p] = dup2(bv.w);
            }
        }
        const float* h0c = h0buf + ((t + 1) & 1) * 1024;
        #pragma unroll 8
        for (int k = 0; k < HH; k++) {
            float4 wa = w1i[(k << 6) + h];
            float4 wb = w1h[(k << 6) + h];
            ulonglong2 av = *(const ulonglong2*)(h0c + (k << 4) + r0);
            ulonglong2 uv = *(const ulonglong2*)(h1s + (k << 4) + r0);
            unsigned long long wi = dup2(wa.x), wf = dup2(wa.y),
                               wg = dup2(wa.z), wo = dup2(wa.w);
            fma2(aI[0], wi, av.x); fma2(aI[1], wi, av.y);
            fma2(aF[0], wf, av.x); fma2(aF[1], wf, av.y);
            fma2(aG[0], wg, av.x); fma2(aG[1], wg, av.y);
            fma2(aO[0], wo, av.x); fma2(aO[1], wo, av.y);
            wi = dup2(wb.x); wf = dup2(wb.y); wg = dup2(wb.z); wo = dup2(wb.w);
            fma2(aI[0], wi, uv.x); fma2(aI[1], wi, uv.y);
            fma2(aF[0], wf, uv.x); fma2(aF[1], wf, uv.y);
            fma2(aG[0], wg, uv.x); fma2(aG[1], wg, uv.y);
            fma2(aO[0], wo, uv.x); fma2(aO[1], wo, uv.y);
        }
        float h1n[4];
        #pragma unroll
        for (int p = 0; p < 2; p++)
            lstm_act_pair(aI[p], aF[p], aG[p], aO[p], c1, h1n, 2 * p);

        __syncthreads();   // all reads of h1s(t-1) done before overwrite
        *(float4*)(h1s + (h << 4) + r0) = make_float4(h1n[0], h1n[1], h1n[2], h1n[3]);
    }
    __syncthreads();

    // ---- FC head: out[b][o] = h1 . fc_w[o] + fc_b[o] ----
    for (int idx = tid; idx < 16 * OO; idx += 256) {
        int o = idx >> 4, r = idx & 15;
        float s = fc_b[o];
        #pragma unroll 8
        for (int k = 0; k < HH; k++)
            s += fc_w[o * HH + k] * h1s[(k << 4) + r];
        out[(size_t)(bR0 + r) * OO + o] = s;
    }
}

// =====================================================================
extern "C" void kernel_launch(void* const* d_in, const int* in_sizes, int n_in,
                              void* d_out, int out_size)
{
    (void)in_sizes; (void)n_in; (void)out_size;
    const float* x     = (const float*)d_in[0];
    const float* w_ih0 = (const float*)d_in[1];
    const float* w_hh0 = (const float*)d_in[2];
    const float* b_ih0 = (const float*)d_in[3];
    const float* b_hh0 = (const float*)d_in[4];
    const float* w_ih1 = (const float*)d_in[5];
    const float* w_hh1 = (const float*)d_in[6];
    const float* b_ih1 = (const float*)d_in[7];
    const float* b_hh1 = (const float*)d_in[8];
    const float* fc_w  = (const float*)d_in[9];
    const float* fc_b  = (const float*)d_in[10];
    float* out = (float*)d_out;

    cudaFuncSetAttribute(k1_inproj, cudaFuncAttributeMaxDynamicSharedMemorySize, K1_SMEM);
    cudaFuncSetAttribute(k2_rnn,    cudaFuncAttributeMaxDynamicSharedMemorySize, K2_SMEM);

    k1_inproj<<<(BB * TT) / 64, 512, K1_SMEM>>>(x, w_ih0, b_ih0, b_hh0);
    k2_rnn<<<BB / 16, 256, K2_SMEM>>>(w_hh0, w_ih1, w_hh1, b_ih1, b_hh1,
                                      fc_w, fc_b, out);
}

// round 3
// speedup vs baseline: 1.2423x; 1.2423x over previous
#include <cuda_runtime.h>
#include <cstdint>

// MusicRNN: 2-layer LSTM (B=2048, T=256, I=88, H=64) + FC(64->13)
//   K1: precompute layer-0 input projection P0 (gate-interleaved float4).
//       Coalesced global loads + padded SMEM transpose (no 32-way conflicts).
//   K2: persistent fused recurrence. 128 CTAs x 256 threads (2 warps/SMSP),
//       K-SPLIT across half-warps: lanes 0-15 sum k=0..31, lanes 16-31 sum
//       k=32..63, combined via shfl.bfly(16)+add.f32x2. Crossbar traffic stays
//       at RG=2 level while warp count doubles. Weights in SMEM (gate-packed
//       float4, row stride 65), h via SMEM double buffer, c in registers.

#define BB 2048
#define TT 256
#define II 88
#define HH 64
#define OO 13

__device__ float4 g_P0[(size_t)TT * BB * HH];   // [T][B][H] gate pre-acts

typedef unsigned long long ull;

// ---------------- packed f32x2 helpers ----------------
__device__ __forceinline__ ull pack2(float lo, float hi) {
    ull r; asm("mov.b64 %0, {%1, %2};" : "=l"(r) : "f"(lo), "f"(hi)); return r;
}
__device__ __forceinline__ ull dup2(float v) {
    ull r; asm("mov.b64 %0, {%1, %1};" : "=l"(r) : "f"(v)); return r;
}
__device__ __forceinline__ void unpack2(ull v, float& lo, float& hi) {
    asm("mov.b64 {%0, %1}, %2;" : "=f"(lo), "=f"(hi) : "l"(v));
}
__device__ __forceinline__ void fma2(ull& d, ull a, ull b) {
    asm("fma.rn.f32x2 %0, %1, %2, %0;" : "+l"(d) : "l"(a), "l"(b));
}
__device__ __forceinline__ ull add2(ull a, ull b) {
    ull r; asm("add.rn.f32x2 %0, %1, %2;" : "=l"(r) : "l"(a), "l"(b)); return r;
}
// butterfly-16 exchange + add (combines the two k-halves of a warp)
__device__ __forceinline__ ull bfly16_add(ull v) {
    unsigned lo, hi, lo2, hi2;
    asm("mov.b64 {%0, %1}, %2;" : "=r"(lo), "=r"(hi) : "l"(v));
    asm("shfl.sync.bfly.b32 %0, %1, 16, 0x1f, 0xffffffff;" : "=r"(lo2) : "r"(lo));
    asm("shfl.sync.bfly.b32 %0, %1, 16, 0x1f, 0xffffffff;" : "=r"(hi2) : "r"(hi));
    ull o; asm("mov.b64 %0, {%1, %2};" : "=l"(o) : "r"(lo2), "r"(hi2));
    return add2(v, o);
}

// ---------------- activations (MUFU-based, ~1e-7 rel err) ----------------
__device__ __forceinline__ float sigf(float x) {
    return __fdividef(1.0f, 1.0f + __expf(-x));
}
__device__ __forceinline__ float tanhf_fast(float x) {
    return __fdividef(2.0f, 1.0f + __expf(-2.0f * x)) - 1.0f;
}

__device__ __forceinline__ void lstm_act_pair(
    ull aI, ull aF, ull aG, ull aO, float* c, float* hn, int r)
{
    float i0, i1, f0, f1, g0, g1, o0, o1;
    unpack2(aI, i0, i1); unpack2(aF, f0, f1);
    unpack2(aG, g0, g1); unpack2(aO, o0, o1);
    float cc0 = sigf(f0) * c[r]     + sigf(i0) * tanhf_fast(g0);
    float cc1 = sigf(f1) * c[r + 1] + sigf(i1) * tanhf_fast(g1);
    c[r]      = cc0;  hn[r]     = sigf(o0) * tanhf_fast(cc0);
    c[r + 1]  = cc1;  hn[r + 1] = sigf(o1) * tanhf_fast(cc1);
}

// =====================================================================
// K1: input projection.  Grid: B*T/64 CTAs, 512 threads.
//     Weight SMEM row stride 65 float4 (fill: 4-way conflict max);
//     xs row stride 66 floats (fill: 2-way conflict max). All LDG coalesced.
// =====================================================================
#define K1_W4   (II * 65)                 // 5720 float4
#define K1_SMEM ((K1_W4 + 64) * 16 + II * 66 * 4)   // 115776 B

__global__ void __launch_bounds__(512) k1_inproj(
    const float* __restrict__ x, const float* __restrict__ w_ih0,
    const float* __restrict__ b_ih0, const float* __restrict__ b_hh0)
{
    extern __shared__ float4 sm4[];
    float4* w0p = sm4;                       // [88][65] gate-packed (padded)
    float4* b0p = sm4 + K1_W4;               // [64]
    float*  xs  = (float*)(sm4 + K1_W4 + 64);   // [88][66] k-major (padded)
    float*  ws  = (float*)w0p;

    const int tid = threadIdx.x;

    // coalesced weight load + padded transpose:  w_ih0 is [256][88]
    for (int idx = tid; idx < 256 * II; idx += 512) {
        int g = idx / II, k = idx - g * II;
        int h = g & 63, gate = g >> 6;
        ws[(k * 65 + h) * 4 + gate] = w_ih0[idx];
    }
    if (tid < HH) {
        float4 v;
        v.x = b_ih0[tid]       + b_hh0[tid];
        v.y = b_ih0[tid +  64] + b_hh0[tid +  64];
        v.z = b_ih0[tid + 128] + b_hh0[tid + 128];
        v.w = b_ih0[tid + 192] + b_hh0[tid + 192];
        b0p[tid] = v;
    }
    const int bt0 = blockIdx.x * 64;   // 64 consecutive (b*T+t) rows
    for (int idx = tid; idx < 64 * II; idx += 512) {
        int r = idx / II, k = idx - r * II;
        xs[k * 66 + r] = x[(size_t)bt0 * II + idx];
    }
    __syncthreads();

    const int h  = tid & 63;
    const int r0 = (tid >> 6) * 8;   // 8 rows per thread

    ull aI[4], aF[4], aG[4], aO[4];
    {
        float4 bv = b0p[h];
        #pragma unroll
        for (int p = 0; p < 4; p++) {
            aI[p] = dup2(bv.x); aF[p] = dup2(bv.y);
            aG[p] = dup2(bv.z); aO[p] = dup2(bv.w);
        }
    }
    #pragma unroll 4
    for (int k = 0; k < II; k++) {
        float4 w = w0p[k * 65 + h];
        ull wi = dup2(w.x), wf = dup2(w.y), wg = dup2(w.z), wo = dup2(w.w);
        const ull* hv = (const ull*)&xs[k * 66 + r0];   // broadcast loads
        ull v0 = hv[0], v1 = hv[1], v2 = hv[2], v3 = hv[3];
        fma2(aI[0], wi, v0); fma2(aI[1], wi, v1); fma2(aI[2], wi, v2); fma2(aI[3], wi, v3);
        fma2(aF[0], wf, v0); fma2(aF[1], wf, v1); fma2(aF[2], wf, v2); fma2(aF[3], wf, v3);
        fma2(aG[0], wg, v0); fma2(aG[1], wg, v1); fma2(aG[2], wg, v2); fma2(aG[3], wg, v3);
        fma2(aO[0], wo, v0); fma2(aO[1], wo, v1); fma2(aO[2], wo, v2); fma2(aO[3], wo, v3);
    }
    #pragma unroll
    for (int p = 0; p < 4; p++) {
        float i0, i1, f0, f1, g0, g1, o0, o1;
        unpack2(aI[p], i0, i1); unpack2(aF[p], f0, f1);
        unpack2(aG[p], g0, g1); unpack2(aO[p], o0, o1);
        int bt = bt0 + r0 + 2 * p;
        int t = bt & (TT - 1), b = bt >> 8;
        g_P0[((size_t)t * BB + b) * HH + h] = make_float4(i0, f0, g0, o0);
        bt++; t = bt & (TT - 1); b = bt >> 8;
        g_P0[((size_t)t * BB + b) * HH + h] = make_float4(i1, f1, g1, o1);
    }
}

// =====================================================================
// K2: persistent fused recurrence + FC.
//     256 threads: warp w = [rg = w>>2][hb = w&3]; lane = [kh = l>>4][hl = l&15]
//     h = hb*16+hl owns 4 gates x 8 rows (r0 = rg*8), summing k-half kh.
// =====================================================================
#define K2_W4   (HH * 65)                        // 4160 float4 per matrix
#define K2_SMEM ((3 * K2_W4 + 64) * 16 + (2048 + 1024) * 4)   // 212992 B

__global__ void __launch_bounds__(256) k2_rnn(
    const float* __restrict__ w_hh0, const float* __restrict__ w_ih1,
    const float* __restrict__ w_hh1, const float* __restrict__ b_ih1,
    const float* __restrict__ b_hh1, const float* __restrict__ fc_w,
    const float* __restrict__ fc_b, float* __restrict__ out)
{
    extern __shared__ float4 sm4[];
    float4* w0p = sm4;                     // [64][65] gate-packed W_hh0
    float4* w1i = sm4 + K2_W4;             // W_ih1
    float4* w1h = sm4 + 2 * K2_W4;         // W_hh1
    float4* b1p = sm4 + 3 * K2_W4;         // [64]
    float*  h0buf = (float*)(sm4 + 3 * K2_W4 + 64);  // 2 x [64][16]
    float*  h1s   = h0buf + 2048;                    // [64][16]

    const int tid = threadIdx.x;

    // coalesced weight loads + padded transpose: each matrix is [256][64]
    {
        float* s0 = (float*)w0p; float* s1 = (float*)w1i; float* s2 = (float*)w1h;
        for (int idx = tid; idx < 256 * HH; idx += 256) {
            int g = idx >> 6, k = idx & 63;
            int h = g & 63, gate = g >> 6;
            int sidx = (k * 65 + h) * 4 + gate;
            s0[sidx] = w_hh0[idx];
            s1[sidx] = w_ih1[idx];
            s2[sidx] = w_hh1[idx];
        }
    }
    if (tid < HH) {
        float4 v;
        v.x = b_ih1[tid]       + b_hh1[tid];
        v.y = b_ih1[tid +  64] + b_hh1[tid +  64];
        v.z = b_ih1[tid + 128] + b_hh1[tid + 128];
        v.w = b_ih1[tid + 192] + b_hh1[tid + 192];
        b1p[tid] = v;
    }
    for (int idx = tid; idx < 3072; idx += 256) h0buf[idx] = 0.0f;
    __syncthreads();

    const int lane = tid & 31;
    const int kh   = lane >> 4;                       // k-half: 0 or 1
    const int h    = ((tid >> 5) & 3) * 16 + (lane & 15);
    const int r0   = (tid >> 7) * 8;                  // rowgroup: rows r0..r0+7
    const int kb   = kh * 32;                         // k base for this half
    const int bR0  = blockIdx.x * 16;

    float c0[8], c1[8];
    #pragma unroll
    for (int r = 0; r < 8; r++) { c0[r] = 0.0f; c1[r] = 0.0f; }

    // P0 prefetch (kh==0 lanes only; kh==1 accs init to zero)
    float4 xg[8];
    if (kh == 0) {
        #pragma unroll
        for (int j = 0; j < 8; j++)
            xg[j] = g_P0[(size_t)(bR0 + r0 + j) * HH + h];
    }

    for (int t = 0; t < TT; t++) {
        ull aI[4], aF[4], aG[4], aO[4];
        if (kh == 0) {
            #pragma unroll
            for (int p = 0; p < 4; p++) {
                aI[p] = pack2(xg[2 * p].x, xg[2 * p + 1].x);
                aF[p] = pack2(xg[2 * p].y, xg[2 * p + 1].y);
                aG[p] = pack2(xg[2 * p].z, xg[2 * p + 1].z);
                aO[p] = pack2(xg[2 * p].w, xg[2 * p + 1].w);
            }
            // prefetch P0 for t+1 (overlaps layer-0 matvec)
            int tn = (t + 1 < TT) ? (t + 1) : t;
            size_t base = ((size_t)tn * BB + bR0 + r0) * HH + h;
            #pragma unroll
            for (int j = 0; j < 8; j++) xg[j] = g_P0[base + (size_t)j * HH];
        } else {
            #pragma unroll
            for (int p = 0; p < 4; p++) { aI[p] = 0; aF[p] = 0; aG[p] = 0; aO[p] = 0; }
        }

        // ---- layer 0: gates += h0(t-1) @ W_hh0^T  (this thread's k-half) ----
        const float* hp = h0buf + (t & 1) * 1024;
        #pragma unroll 8
        for (int k = 0; k < 32; k++) {
            int kk = kb + k;
            float4 w = w0p[kk * 65 + h];
            ull wi = dup2(w.x), wf = dup2(w.y), wg = dup2(w.z), wo = dup2(w.w);
            const ull* hv = (const ull*)(hp + (kk << 4) + r0);
            ull v0 = hv[0], v1 = hv[1], v2 = hv[2], v3 = hv[3];
            fma2(aI[0], wi, v0); fma2(aI[1], wi, v1); fma2(aI[2], wi, v2); fma2(aI[3], wi, v3);
            fma2(aF[0], wf, v0); fma2(aF[1], wf, v1); fma2(aF[2], wf, v2); fma2(aF[3], wf, v3);
            fma2(aG[0], wg, v0); fma2(aG[1], wg, v1); fma2(aG[2], wg, v2); fma2(aG[3], wg, v3);
            fma2(aO[0], wo, v0); fma2(aO[1], wo, v1); fma2(aO[2], wo, v2); fma2(aO[3], wo, v3);
        }
        // combine k-halves
        #pragma unroll
        for (int p = 0; p < 4; p++) {
            aI[p] = bfly16_add(aI[p]); aF[p] = bfly16_add(aF[p]);
            aG[p] = bfly16_add(aG[p]); aO[p] = bfly16_add(aO[p]);
        }
        float h0n[8];
        #pragma unroll
        for (int p = 0; p < 4; p++)
            lstm_act_pair(aI[p], aF[p], aG[p], aO[p], c0, h0n, 2 * p);

        if (kh == 0) {
            float* hw = h0buf + ((t + 1) & 1) * 1024 + (h << 4) + r0;
            *(float4*)hw       = make_float4(h0n[0], h0n[1], h0n[2], h0n[3]);
            *((float4*)hw + 1) = make_float4(h0n[4], h0n[5], h0n[6], h0n[7]);
        }
        __syncthreads();

        // ---- layer 1: gates = b1 + h0(t) @ W_ih1^T + h1(t-1) @ W_hh1^T ----
        if (kh == 0) {
            float4 bv = b1p[h];
            #pragma unroll
            for (int p = 0; p < 4; p++) {
                aI[p] = dup2(bv.x); aF[p] = dup2(bv.y);
                aG[p] = dup2(bv.z); aO[p] = dup2(bv.w);
            }
        } else {
            #pragma unroll
            for (int p = 0; p < 4; p++) { aI[p] = 0; aF[p] = 0; aG[p] = 0; aO[p] = 0; }
        }
        const float* h0c = h0buf + ((t + 1) & 1) * 1024;
        #pragma unroll 4
        for (int k = 0; k < 32; k++) {
            int kk = kb + k;
            float4 wa = w1i[kk * 65 + h];
            float4 wb = w1h[kk * 65 + h];
            const ull* av = (const ull*)(h0c + (kk << 4) + r0);
            const ull* uv = (const ull*)(h1s + (kk << 4) + r0);
            ull a0 = av[0], a1 = av[1], a2 = av[2], a3 = av[3];
            ull u0 = uv[0], u1 = uv[1], u2 = uv[2], u3 = uv[3];
            ull wi = dup2(wa.x), wf = dup2(wa.y), wg = dup2(wa.z), wo = dup2(wa.w);
            fma2(aI[0], wi, a0); fma2(aI[1], wi, a1); fma2(aI[2], wi, a2); fma2(aI[3], wi, a3);
            fma2(aF[0], wf, a0); fma2(aF[1], wf, a1); fma2(aF[2], wf, a2); fma2(aF[3], wf, a3);
            fma2(aG[0], wg, a0); fma2(aG[1], wg, a1); fma2(aG[2], wg, a2); fma2(aG[3], wg, a3);
            fma2(aO[0], wo, a0); fma2(aO[1], wo, a1); fma2(aO[2], wo, a2); fma2(aO[3], wo, a3);
            wi = dup2(wb.x); wf = dup2(wb.y); wg = dup2(wb.z); wo = dup2(wb.w);
            fma2(aI[0], wi, u0); fma2(aI[1], wi, u1); fma2(aI[2], wi, u2); fma2(aI[3], wi, u3);
            fma2(aF[0], wf, u0); fma2(aF[1], wf, u1); fma2(aF[2], wf, u2); fma2(aF[3], wf, u3);
            fma2(aG[0], wg, u0); fma2(aG[1], wg, u1); fma2(aG[2], wg, u2); fma2(aG[3], wg, u3);
            fma2(aO[0], wo, u0); fma2(aO[1], wo, u1); fma2(aO[2], wo, u2); fma2(aO[3], wo, u3);
        }
        #pragma unroll
        for (int p = 0; p < 4; p++) {
            aI[p] = bfly16_add(aI[p]); aF[p] = bfly16_add(aF[p]);
            aG[p] = bfly16_add(aG[p]); aO[p] = bfly16_add(aO[p]);
        }
        float h1n[8];
        #pragma unroll
        for (int p = 0; p < 4; p++)
            lstm_act_pair(aI[p], aF[p], aG[p], aO[p], c1, h1n, 2 * p);

        __syncthreads();   // all reads of h1s(t-1) done before overwrite
        if (kh == 0) {
            float* hw1 = h1s + (h << 4) + r0;
            *(float4*)hw1       = make_float4(h1n[0], h1n[1], h1n[2], h1n[3]);
            *((float4*)hw1 + 1) = make_float4(h1n[4], h1n[5], h1n[6], h1n[7]);
        }
    }
    __syncthreads();

    // ---- FC head: out[b][o] = h1 . fc_w[o] + fc_b[o] ----
    for (int idx = tid; idx < 16 * OO; idx += 256) {
        int o = idx >> 4, r = idx & 15;
        float s = fc_b[o];
        #pragma unroll 8
        for (int k = 0; k < HH; k++)
            s += fc_w[o * HH + k] * h1s[(k << 4) + r];
        out[(size_t)(bR0 + r) * OO + o] = s;
    }
}

// =====================================================================
extern "C" void kernel_launch(void* const* d_in, const int* in_sizes, int n_in,
                              void* d_out, int out_size)
{
    (void)in_sizes; (void)n_in; (void)out_size;
    const float* x     = (const float*)d_in[0];
    const float* w_ih0 = (const float*)d_in[1];
    const float* w_hh0 = (const float*)d_in[2];
    const float* b_ih0 = (const float*)d_in[3];
    const float* b_hh0 = (const float*)d_in[4];
    const float* w_ih1 = (const float*)d_in[5];
    const float* w_hh1 = (const float*)d_in[6];
    const float* b_ih1 = (const float*)d_in[7];
    const float* b_hh1 = (const float*)d_in[8];
    const float* fc_w  = (const float*)d_in[9];
    const float* fc_b  = (const float*)d_in[10];
    float* out = (float*)d_out;

    cudaFuncSetAttribute(k1_inproj, cudaFuncAttributeMaxDynamicSharedMemorySize, K1_SMEM);
    cudaFuncSetAttribute(k2_rnn,    cudaFuncAttributeMaxDynamicSharedMemorySize, K2_SMEM);

    k1_inproj<<<(BB * TT) / 64, 512, K1_SMEM>>>(x, w_ih0, b_ih0, b_hh0);
    k2_rnn<<<BB / 16, 256, K2_SMEM>>>(w_hh0, w_ih1, w_hh1, b_ih1, b_hh1,
                                      fc_w, fc_b, out);
}